// round 15
// baseline (speedup 1.0000x reference)
#include <cuda_runtime.h>
#include <cuda_fp16.h>
#include <cstdint>

// Problem dims
#define Ldim 1024
#define Sdim 1024
#define Nb   4
#define Edim 1024
#define Hh   16
#define HDim 64
#define Bt   64      // Nb*Hh
#define MROWS 4096   // Ldim*Nb

// d_out layout (fp32): [0..4194304) out(L,N,E) | [..8388608) attn(N,L,S) | [..12582912) sig(N,L,S)
#define OUT_ATTN 4194304
#define OUT_SIG  8388608

// ------------------------------- scratch ----------------------------------
__device__ float g_invZ[(size_t)Bt * Ldim];
__device__ float g_Zpart[(size_t)Bt * Ldim * 16];              // 16 s-chunks of 64
__device__ __half g_v[(size_t)Bt * Sdim * HDim];               // [b][s][d] fp16
__device__ __half g_eh[(size_t)Bt * Ldim * Sdim];              // e = exp(score) fp16
__device__ __half g_vth[(size_t)Bt * HDim * Sdim];             // v^T fp16 [b][d][s]
__device__ __half g_qh[(size_t)Bt * Sdim * HDim];              // q fp16 (scaled)
__device__ __half g_kh[(size_t)Bt * Sdim * HDim];              // k fp16
__device__ __half g_inh[(size_t)3 * MROWS * Edim];             // inputs fp16
__device__ __half g_wh[(size_t)4 * Edim * Edim];               // weights fp16 (w_in ++ w_out)
__device__ __half g_ch[(size_t)MROWS * Edim];                  // ctx fp16

// ------------------------------ helpers ------------------------------------
__device__ __forceinline__ uint32_t smem_u32(const void* p) {
    uint32_t a; asm("{ .reg .u64 t; cvta.to.shared.u64 t, %1; cvt.u32.u64 %0, t; }" : "=r"(a) : "l"(p));
    return a;
}
__device__ __forceinline__ void ldsm4(uint32_t* r, uint32_t addr) {
    asm volatile("ldmatrix.sync.aligned.m8n8.x4.shared.b16 {%0,%1,%2,%3}, [%4];"
                 : "=r"(r[0]), "=r"(r[1]), "=r"(r[2]), "=r"(r[3]) : "r"(addr));
}
__device__ __forceinline__ void mma_f16(float* d, const uint32_t* a, uint32_t b0, uint32_t b1) {
    asm volatile("mma.sync.aligned.m16n8k16.row.col.f32.f16.f16.f32 "
                 "{%0,%1,%2,%3}, {%4,%5,%6,%7}, {%8,%9}, {%0,%1,%2,%3};"
                 : "+f"(d[0]), "+f"(d[1]), "+f"(d[2]), "+f"(d[3])
                 : "r"(a[0]), "r"(a[1]), "r"(a[2]), "r"(a[3]), "r"(b0), "r"(b1));
}
__device__ __forceinline__ void cpa16(uint32_t saddr, const void* g) {
    asm volatile("cp.async.cg.shared.global [%0], [%1], 16;" :: "r"(saddr), "l"(g));
}
#define CP_COMMIT() asm volatile("cp.async.commit_group;" ::: "memory")
#define CP_WAIT0()  asm volatile("cp.async.wait_group 0;" ::: "memory")
#define CP_WAIT1()  asm volatile("cp.async.wait_group 1;" ::: "memory")

// ---------------------------------------------------------------------------
// convert: fp32 -> fp16 for inputs and weights
// ---------------------------------------------------------------------------
__global__ void __launch_bounds__(256) convert_split(const float* __restrict__ q,
                                                     const float* __restrict__ k,
                                                     const float* __restrict__ v,
                                                     const float* __restrict__ w_in,
                                                     const float* __restrict__ w_out)
{
    const size_t u = (size_t)blockIdx.x * 256 + threadIdx.x;   // float4 index
    float4 x;
    __half* dst;
    size_t e;
    if (u < 3145728) {
        const size_t z = u >> 20, off = u & 1048575;
        x = ((const float4*)((z == 0) ? q : (z == 1) ? k : v))[off];
        dst = g_inh; e = u * 4;
    } else {
        const size_t uw = u - 3145728;
        x = (uw < 786432) ? ((const float4*)w_in)[uw]
                          : ((const float4*)w_out)[uw - 786432];
        dst = g_wh; e = uw * 4;
    }
    __half h[4];
    h[0] = __float2half_rn(x.x); h[1] = __float2half_rn(x.y);
    h[2] = __float2half_rn(x.z); h[3] = __float2half_rn(x.w);
    *(uint2*)(dst + e) = *(const uint2*)h;
}

// ---------------------------------------------------------------------------
// HMMA fp16 NT GEMM 128x128 tile, K=1024, BK=32, pure fp16.
// cp.async double-buffered. smem: A 2x10240; B 2x10240 at 20480. 40960 B.
// MODE 0: QKV (z): z=0 -> q (scaled), z=1 -> k, z=2 -> v.
// MODE 1: out projection -> Cout + bias (fp32).
// ---------------------------------------------------------------------------
#define HMMA_SMEM 40960

template <int MODE>
__global__ void __launch_bounds__(256, 2) hmma_gemm(const float* __restrict__ biasIn,
                                                    float* __restrict__ Cout)
{
    extern __shared__ char smem[];
    const int tid = threadIdx.x;
    const int lane = tid & 31;
    const int wid = tid >> 5;
    const int wm = wid & 3;
    const int wn = wid >> 2;
    const int bm = blockIdx.y * 128;
    const int bn = blockIdx.x * 128;
    const int z  = (MODE == 0) ? blockIdx.z : 0;

    const __half* A;
    const __half* B;
    const float* bias;
    if (MODE == 0) {
        A = g_inh + (size_t)z * 4194304;
        B = g_wh + (size_t)z * 1048576;
        bias = biasIn + z * Edim;
    } else {
        A = g_ch;
        B = g_wh + 3145728;
        bias = biasIn;
    }

    const int r0 = tid >> 2;
    const int gc = tid & 3;
    const uint32_t sb = smem_u32(smem);
    const uint32_t a_lane = (uint32_t)((wm * 32 + (lane & 15)) * 80 + (lane >> 4) * 16);
    const uint32_t b_lane = (uint32_t)((wn * 64 + (lane >> 4) * 8 + (lane & 7)) * 80
                                       + ((lane >> 3) & 1) * 16);

    float acc[2][8][4];
#pragma unroll
    for (int mt = 0; mt < 2; ++mt)
#pragma unroll
        for (int nt = 0; nt < 8; ++nt)
#pragma unroll
            for (int q = 0; q < 4; ++q) acc[mt][nt][q] = 0.f;

    auto issue = [&](int c, int buf) {
        const int k0 = c * 32;
#pragma unroll
        for (int i = 0; i < 2; ++i) {
            const int row = r0 + 64 * i;
            cpa16(sb + (uint32_t)(buf * 10240 + row * 80 + gc * 16),
                  A + (size_t)(bm + row) * Edim + k0 + gc * 8);
            cpa16(sb + (uint32_t)(20480 + buf * 10240 + row * 80 + gc * 16),
                  B + (size_t)(bn + row) * Edim + k0 + gc * 8);
        }
        CP_COMMIT();
    };

    issue(0, 0);
    issue(1, 1);

    for (int c = 0; c < 32; ++c) {
        if (c < 31) { CP_WAIT1(); } else { CP_WAIT0(); }
        __syncthreads();
        const int buf = c & 1;
        const uint32_t abase = sb + (uint32_t)buf * 10240u;
        const uint32_t bbase = sb + 20480u + (uint32_t)buf * 10240u;

#pragma unroll
        for (int k16 = 0; k16 < 2; ++k16) {
            const uint32_t koff = (uint32_t)(k16 * 32);
            uint32_t af[2][4];
#pragma unroll
            for (int mt = 0; mt < 2; ++mt)
                ldsm4(af[mt], abase + a_lane + (uint32_t)(mt * 1280) + koff);
#pragma unroll
            for (int p = 0; p < 4; ++p) {
                uint32_t bf[4];
                ldsm4(bf, bbase + b_lane + (uint32_t)(p * 1280) + koff);
#pragma unroll
                for (int mt = 0; mt < 2; ++mt) {
                    mma_f16(acc[mt][2 * p],     af[mt], bf[0], bf[1]);
                    mma_f16(acc[mt][2 * p + 1], af[mt], bf[2], bf[3]);
                }
            }
        }
        __syncthreads();
        if (c + 2 < 32) issue(c + 2, buf);
    }

    const int g  = lane >> 2;
    const int t4 = lane & 3;
#pragma unroll
    for (int mt = 0; mt < 2; ++mt) {
#pragma unroll
        for (int nt = 0; nt < 8; ++nt) {
            const int cc = bn + wn * 64 + nt * 8 + 2 * t4;
            const int rr = bm + wm * 32 + mt * 16 + g;
            const float b0 = bias[cc], b1 = bias[cc + 1];
            const float* d = acc[mt][nt];
            if (MODE == 0) {
                const int h = cc >> 6, dc = cc & 63;
                const float scale = (z == 0) ? 0.125f : 1.f;
                __half* dst = (z == 0) ? g_qh : (z == 1) ? g_kh : g_v;
#pragma unroll
                for (int rh = 0; rh < 2; ++rh) {
                    const int r = rr + 8 * rh;
                    const int l = r >> 2, n = r & 3;
                    const size_t idx = (((size_t)(n * Hh + h)) * Sdim + l) * HDim + dc;
                    *(__half2*)(dst + idx) =
                        __floats2half2_rn((d[2 * rh + 0] + b0) * scale,
                                          (d[2 * rh + 1] + b1) * scale);
                }
            } else {
#pragma unroll
                for (int rh = 0; rh < 2; ++rh) {
                    const int r = rr + 8 * rh;
                    float2 o;
                    o.x = d[2 * rh + 0] + b0;
                    o.y = d[2 * rh + 1] + b1;
                    *(float2*)(Cout + (size_t)r * Edim + cc) = o;
                }
            }
        }
    }
}

// ---------------------------------------------------------------------------
// transpose v: fp16 [b][s][d] -> fp16 [b][d][s]
// ---------------------------------------------------------------------------
__global__ void __launch_bounds__(256) transpose_v()
{
    __shared__ __half tile[64][66];
    const int b = blockIdx.y;
    const int s0 = blockIdx.x * 64;
    const int tid = threadIdx.x;

#pragma unroll
    for (int it = 0; it < 8; ++it) {
        const int idx2 = tid + 256 * it;         // 0..2047
        const int sl = idx2 >> 5, dp = (idx2 & 31) << 1;
        const __half2 v2 = *(const __half2*)(g_v + ((size_t)b * Sdim + s0 + sl) * HDim + dp);
        tile[sl][dp] = v2.x;
        tile[sl][dp + 1] = v2.y;
    }
    __syncthreads();
#pragma unroll
    for (int it = 0; it < 8; ++it) {
        const int idx2 = tid + 256 * it;
        const int d = idx2 >> 5, slp = (idx2 & 31) << 1;
        __half2 o; o.x = tile[slp][d]; o.y = tile[slp + 1][d];
        *(__half2*)(g_vth + ((size_t)b * HDim + d) * Sdim + s0 + slp) = o;
    }
}

// ---------------------------------------------------------------------------
// scores_exp: one 128x64 e-tile per CTA, grid (16 sc, 8 lt, 64 b). K=64.
// Pure fp16 MMA, occ 3. e staged in smem (144B row stride) then coalesced.
// smem: Q 2kc x 10240 at 0; K 2kc x 5120 at 20480 | (after MMA) e-tile
// 128x144B at 0; zbuf 2x128 f32 at 30720. Total 31744.
// ---------------------------------------------------------------------------
#define SCORES_SMEM 31744

__global__ void __launch_bounds__(256, 3) scores_exp()
{
    extern __shared__ char smem[];
    const int tid = threadIdx.x;
    const int lane = tid & 31;
    const int wid = tid >> 5;
    const int wm = wid & 3;
    const int wn = wid >> 2;
    const int b  = blockIdx.z;
    const int bm = blockIdx.y * 128;
    const int bn = blockIdx.x * 64;
    const int sc = blockIdx.x;

    const __half* Qh = g_qh + (size_t)b * Sdim * HDim;
    const __half* Kh = g_kh + (size_t)b * Sdim * HDim;

    const int r0 = tid >> 2;          // 0..63
    const int gc = tid & 3;
    const uint32_t sb = smem_u32(smem);
    const uint32_t a_lane = (uint32_t)((wm * 32 + (lane & 15)) * 80 + (lane >> 4) * 16);
    const uint32_t b_lane = (uint32_t)((wn * 32 + (lane >> 4) * 8 + (lane & 7)) * 80
                                       + ((lane >> 3) & 1) * 16);
    const int g  = lane >> 2;
    const int t4 = lane & 3;

    // load Q (128 rows) + K (64 rows, first 128 threads) per kc slab
#pragma unroll
    for (int kc = 0; kc < 2; ++kc) {
#pragma unroll
        for (int i = 0; i < 2; ++i) {
            const int row = r0 + 64 * i;
            cpa16(sb + (uint32_t)(kc * 10240 + row * 80 + gc * 16),
                  Qh + (size_t)(bm + row) * HDim + kc * 32 + gc * 8);
        }
        cpa16(sb + (uint32_t)(20480 + kc * 5120 + r0 * 80 + gc * 16),
              Kh + (size_t)(bn + r0) * HDim + kc * 32 + gc * 8);
    }
    CP_COMMIT();
    CP_WAIT0();
    __syncthreads();

    float acc[2][4][4];
#pragma unroll
    for (int mt = 0; mt < 2; ++mt)
#pragma unroll
        for (int nt = 0; nt < 4; ++nt)
#pragma unroll
            for (int q = 0; q < 4; ++q) acc[mt][nt][q] = 0.f;

#pragma unroll
    for (int kc = 0; kc < 2; ++kc)
#pragma unroll
        for (int k16 = 0; k16 < 2; ++k16) {
            const uint32_t koff = (uint32_t)(k16 * 32);
            uint32_t af[2][4];
#pragma unroll
            for (int mt = 0; mt < 2; ++mt)
                ldsm4(af[mt], sb + (uint32_t)(kc * 10240) + koff + a_lane + (uint32_t)(mt * 1280));
#pragma unroll
            for (int p = 0; p < 2; ++p) {
                uint32_t bf[4];
                ldsm4(bf, sb + 20480u + (uint32_t)(kc * 5120) + koff + b_lane + (uint32_t)(p * 1280));
#pragma unroll
                for (int mt = 0; mt < 2; ++mt) {
                    mma_f16(acc[mt][2 * p],     af[mt], bf[0], bf[1]);
                    mma_f16(acc[mt][2 * p + 1], af[mt], bf[2], bf[3]);
                }
            }
        }

    // Q/K smem dead after this barrier; reuse for the e-tile
    __syncthreads();

    // exp + stage e-tile [128 rows][144B stride]; accumulate partial Z
    float Zp[2][2] = {{0.f, 0.f}, {0.f, 0.f}};
#pragma unroll
    for (int mt = 0; mt < 2; ++mt)
#pragma unroll
        for (int nt = 0; nt < 4; ++nt) {
            const int cl = wn * 32 + nt * 8 + 2 * t4;
            const float* d = acc[mt][nt];
#pragma unroll
            for (int rh = 0; rh < 2; ++rh) {
                const int rl = wm * 32 + mt * 16 + g + 8 * rh;
                const float e0 = __expf(d[2 * rh + 0]);
                const float e1 = __expf(d[2 * rh + 1]);
                Zp[mt][rh] += e0 + e1;
                *(__half2*)(smem + rl * 144 + cl * 2) = __floats2half2_rn(e0, e1);
            }
        }
    __syncthreads();

    // coalesced e-tile store: 128 rows x 128B (uint4 per thread-slot)
#pragma unroll
    for (int it = 0; it < 4; ++it) {
        const int t = tid + 256 * it;
        const int row = t >> 3, seg = t & 7;
        const uint4 v = *(const uint4*)(smem + row * 144 + seg * 16);
        *(uint4*)(g_eh + ((size_t)b * Ldim + bm + row) * Sdim + bn + seg * 8) = v;
    }

    // partial Z reduction (each row's partial over the 64-col chunk)
    float* zbuf = (float*)(smem + 30720);
#pragma unroll
    for (int mt = 0; mt < 2; ++mt)
#pragma unroll
        for (int rh = 0; rh < 2; ++rh) {
            float zv = Zp[mt][rh];
            zv += __shfl_xor_sync(0xffffffffu, zv, 1);
            zv += __shfl_xor_sync(0xffffffffu, zv, 2);
            if (t4 == 0) zbuf[wn * 128 + wm * 32 + mt * 16 + rh * 8 + g] = zv;
        }
    __syncthreads();
    if (tid < 128)
        g_Zpart[(((size_t)b * Ldim) + bm + tid) * 16 + sc] = zbuf[tid] + zbuf[128 + tid];
}

// ---------------------------------------------------------------------------
// averaged attn + sigmoid outputs + invZ finalize. e in fp16.
// grid (512, 4): 2 l-rows per CTA, one uint4 e-load per head per thread.
// ---------------------------------------------------------------------------
__global__ void __launch_bounds__(256) avg_kernel(float* __restrict__ out)
{
    const int l0 = blockIdx.x * 2;
    const int n  = blockIdx.y;
    const int tid = threadIdx.x;
    const int row = tid >> 7;            // 0 or 1
    const int c8  = (tid & 127) * 8;     // 8-half segment within the row
    const int l   = l0 + row;

    __shared__ float sinv[2][16];
    if (tid < 32) {
        const int r = tid >> 4, h = tid & 15;
        const int b = n * 16 + h;
        const float* zp = g_Zpart + (((size_t)b * Ldim) + l0 + r) * 16;
        float z = 0.f;
#pragma unroll
        for (int j = 0; j < 16; ++j) z += zp[j];
        const float iz = 1.0f / z;
        sinv[r][h] = iz;
        g_invZ[(size_t)b * Ldim + l0 + r] = iz;
    }
    __syncthreads();

    float aa[8], ss[8];
#pragma unroll
    for (int j = 0; j < 8; ++j) { aa[j] = 0.f; ss[j] = 0.f; }

    for (int h = 0; h < 16; ++h) {
        const int b = n * 16 + h;
        const float invZ = sinv[row][h];
        const uint4 w = *(const uint4*)(g_eh + ((size_t)b * Ldim + l) * Sdim + c8);
        const uint32_t ws[4] = {w.x, w.y, w.z, w.w};
#pragma unroll
        for (int q = 0; q < 4; ++q) {
            const float2 e2 = __half22float2(*(const __half2*)&ws[q]);
            aa[2 * q + 0] += e2.x * invZ;
            aa[2 * q + 1] += e2.y * invZ;
            ss[2 * q + 0] += __fdividef(e2.x, e2.x + 1.f);
            ss[2 * q + 1] += __fdividef(e2.y, e2.y + 1.f);
        }
    }

    const size_t o = ((size_t)(n * Ldim) + l) * Sdim + c8;
    float4 oa0, oa1, os0, os1;
    oa0.x = aa[0] * 0.0625f; oa0.y = aa[1] * 0.0625f; oa0.z = aa[2] * 0.0625f; oa0.w = aa[3] * 0.0625f;
    oa1.x = aa[4] * 0.0625f; oa1.y = aa[5] * 0.0625f; oa1.z = aa[6] * 0.0625f; oa1.w = aa[7] * 0.0625f;
    os0.x = ss[0] * 0.0625f; os0.y = ss[1] * 0.0625f; os0.z = ss[2] * 0.0625f; os0.w = ss[3] * 0.0625f;
    os1.x = ss[4] * 0.0625f; os1.y = ss[5] * 0.0625f; os1.z = ss[6] * 0.0625f; os1.w = ss[7] * 0.0625f;
    *(float4*)&out[OUT_ATTN + o]     = oa0;
    *(float4*)&out[OUT_ATTN + o + 4] = oa1;
    *(float4*)&out[OUT_SIG  + o]     = os0;
    *(float4*)&out[OUT_SIG  + o + 4] = os1;
}

// ---------------------------------------------------------------------------
// ctx[b] = (e[b] @ v[b]) * invZ : fp16 MMA, 128x64 tile, K=1024, BK=32.
// cp.async double-buffered, occ 3. smem: A 2x10240; B 2x5120. 30720 B.
// ---------------------------------------------------------------------------
#define CTX_SMEM 30720

__global__ void __launch_bounds__(256, 3) ctx_hmma()
{
    extern __shared__ char smem[];
    const int tid = threadIdx.x;
    const int lane = tid & 31;
    const int wid = tid >> 5;
    const int wm = wid & 3;
    const int wn = wid >> 2;
    const int b  = blockIdx.y;
    const int bm = blockIdx.x * 128;

    const __half* Ap = g_eh + (size_t)b * Ldim * Sdim;
    const __half* Bp = g_vth + (size_t)b * HDim * Sdim;

    const int r0 = tid >> 2;
    const int gc = tid & 3;
    const uint32_t sb = smem_u32(smem);
    const uint32_t a_lane = (uint32_t)((wm * 32 + (lane & 15)) * 80 + (lane >> 4) * 16);
    const uint32_t b_lane = (uint32_t)((wn * 32 + (lane >> 4) * 8 + (lane & 7)) * 80
                                       + ((lane >> 3) & 1) * 16);

    float acc[2][4][4];
#pragma unroll
    for (int mt = 0; mt < 2; ++mt)
#pragma unroll
        for (int nt = 0; nt < 4; ++nt)
#pragma unroll
            for (int q = 0; q < 4; ++q) acc[mt][nt][q] = 0.f;

    auto issue = [&](int c, int buf) {
        const int k0 = c * 32;
#pragma unroll
        for (int i = 0; i < 2; ++i) {
            const int row = r0 + 64 * i;
            cpa16(sb + (uint32_t)(buf * 10240 + row * 80 + gc * 16),
                  Ap + (size_t)(bm + row) * Sdim + k0 + gc * 8);
        }
        cpa16(sb + (uint32_t)(20480 + buf * 5120 + r0 * 80 + gc * 16),
              Bp + (size_t)r0 * Sdim + k0 + gc * 8);
        CP_COMMIT();
    };

    issue(0, 0);
    issue(1, 1);

    for (int c = 0; c < 32; ++c) {
        if (c < 31) { CP_WAIT1(); } else { CP_WAIT0(); }
        __syncthreads();
        const int buf = c & 1;
        const uint32_t abase = sb + (uint32_t)buf * 10240u;
        const uint32_t bbase = sb + 20480u + (uint32_t)buf * 5120u;

#pragma unroll
        for (int k16 = 0; k16 < 2; ++k16) {
            const uint32_t koff = (uint32_t)(k16 * 32);
            uint32_t af[2][4];
#pragma unroll
            for (int mt = 0; mt < 2; ++mt)
                ldsm4(af[mt], abase + a_lane + (uint32_t)(mt * 1280) + koff);
#pragma unroll
            for (int p = 0; p < 2; ++p) {
                uint32_t bf[4];
                ldsm4(bf, bbase + b_lane + (uint32_t)(p * 1280) + koff);
#pragma unroll
                for (int mt = 0; mt < 2; ++mt) {
                    mma_f16(acc[mt][2 * p],     af[mt], bf[0], bf[1]);
                    mma_f16(acc[mt][2 * p + 1], af[mt], bf[2], bf[3]);
                }
            }
        }
        __syncthreads();
        if (c + 2 < 32) issue(c + 2, buf);
    }

    const int n = b >> 4;
    const int h = b & 15;
    const int g  = lane >> 2;
    const int t4 = lane & 3;
    float izv[2][2];
#pragma unroll
    for (int mt = 0; mt < 2; ++mt)
#pragma unroll
        for (int rh = 0; rh < 2; ++rh)
            izv[mt][rh] = g_invZ[(size_t)b * Ldim + bm + wm * 32 + mt * 16 + g + 8 * rh];

#pragma unroll
    for (int mt = 0; mt < 2; ++mt)
#pragma unroll
        for (int nt = 0; nt < 4; ++nt) {
            const int cc = wn * 32 + nt * 8 + 2 * t4;
            const int rr = bm + wm * 32 + mt * 16 + g;
            const float* d = acc[mt][nt];
#pragma unroll
            for (int rh = 0; rh < 2; ++rh) {
                const int l = rr + 8 * rh;
                const float iz = izv[mt][rh];
                *(__half2*)(g_ch + ((size_t)(l * Nb + n)) * Edim + h * HDim + cc) =
                    __floats2half2_rn(d[2 * rh + 0] * iz, d[2 * rh + 1] * iz);
            }
        }
}

// ---------------------------------------------------------------------------
extern "C" void kernel_launch(void* const* d_in, const int* in_sizes, int n_in,
                              void* d_out, int out_size)
{
    const float* query = (const float*)d_in[0];
    const float* key   = (const float*)d_in[1];
    const float* value = (const float*)d_in[2];
    const float* w_in  = (const float*)d_in[3];
    const float* b_in  = (const float*)d_in[4];
    const float* w_out = (const float*)d_in[5];
    const float* b_out = (const float*)d_in[6];
    float* out = (float*)d_out;

    cudaFuncSetAttribute(hmma_gemm<0>, cudaFuncAttributeMaxDynamicSharedMemorySize, HMMA_SMEM);
    cudaFuncSetAttribute(hmma_gemm<1>, cudaFuncAttributeMaxDynamicSharedMemorySize, HMMA_SMEM);
    cudaFuncSetAttribute(scores_exp, cudaFuncAttributeMaxDynamicSharedMemorySize, SCORES_SMEM);
    cudaFuncSetAttribute(ctx_hmma, cudaFuncAttributeMaxDynamicSharedMemorySize, CTX_SMEM);

    const dim3 blk(256);

    convert_split<<<16384, blk>>>(query, key, value, w_in, w_out);
    hmma_gemm<0><<<dim3(8, 32, 3), blk, HMMA_SMEM>>>(b_in, nullptr);
    transpose_v<<<dim3(16, Bt), blk>>>();
    scores_exp<<<dim3(16, 8, Bt), blk, SCORES_SMEM>>>();
    avg_kernel<<<dim3(512, Nb), blk>>>(out);
    ctx_hmma<<<dim3(8, Bt), blk, CTX_SMEM>>>();
    hmma_gemm<1><<<dim3(8, 32), blk, HMMA_SMEM>>>(b_out, out);
}

// round 16
// speedup vs baseline: 1.0267x; 1.0267x over previous
#include <cuda_runtime.h>
#include <cuda_fp16.h>
#include <cstdint>

// Problem dims
#define Ldim 1024
#define Sdim 1024
#define Nb   4
#define Edim 1024
#define Hh   16
#define HDim 64
#define Bt   64      // Nb*Hh
#define MROWS 4096   // Ldim*Nb

// d_out layout (fp32): [0..4194304) out(L,N,E) | [..8388608) attn(N,L,S) | [..12582912) sig(N,L,S)
#define OUT_ATTN 4194304
#define OUT_SIG  8388608

// ------------------------------- scratch ----------------------------------
__device__ float g_invZ[(size_t)Bt * Ldim];
__device__ float g_Zpart[(size_t)Bt * Ldim * 8];
__device__ __half g_v[(size_t)Bt * Sdim * HDim];               // [b][s][d] fp16
__device__ __half g_eh[(size_t)Bt * Ldim * Sdim];              // e = exp(score) fp16
__device__ __half g_qh[(size_t)Bt * Sdim * HDim];              // q fp16 (scaled)
__device__ __half g_kh[(size_t)Bt * Sdim * HDim];              // k fp16
__device__ __half g_inh[(size_t)3 * MROWS * Edim];             // inputs fp16
__device__ __half g_wh[(size_t)4 * Edim * Edim];               // weights fp16 (w_in ++ w_out)
__device__ __half g_ch[(size_t)MROWS * Edim];                  // ctx fp16

// ------------------------------ helpers ------------------------------------
__device__ __forceinline__ uint32_t smem_u32(const void* p) {
    uint32_t a; asm("{ .reg .u64 t; cvta.to.shared.u64 t, %1; cvt.u32.u64 %0, t; }" : "=r"(a) : "l"(p));
    return a;
}
__device__ __forceinline__ void ldsm4(uint32_t* r, uint32_t addr) {
    asm volatile("ldmatrix.sync.aligned.m8n8.x4.shared.b16 {%0,%1,%2,%3}, [%4];"
                 : "=r"(r[0]), "=r"(r[1]), "=r"(r[2]), "=r"(r[3]) : "r"(addr));
}
__device__ __forceinline__ void ldsm4t(uint32_t* r, uint32_t addr) {
    asm volatile("ldmatrix.sync.aligned.m8n8.x4.trans.shared.b16 {%0,%1,%2,%3}, [%4];"
                 : "=r"(r[0]), "=r"(r[1]), "=r"(r[2]), "=r"(r[3]) : "r"(addr));
}
__device__ __forceinline__ void mma_f16(float* d, const uint32_t* a, uint32_t b0, uint32_t b1) {
    asm volatile("mma.sync.aligned.m16n8k16.row.col.f32.f16.f16.f32 "
                 "{%0,%1,%2,%3}, {%4,%5,%6,%7}, {%8,%9}, {%0,%1,%2,%3};"
                 : "+f"(d[0]), "+f"(d[1]), "+f"(d[2]), "+f"(d[3])
                 : "r"(a[0]), "r"(a[1]), "r"(a[2]), "r"(a[3]), "r"(b0), "r"(b1));
}
__device__ __forceinline__ void cpa16(uint32_t saddr, const void* g) {
    asm volatile("cp.async.cg.shared.global [%0], [%1], 16;" :: "r"(saddr), "l"(g));
}
#define CP_COMMIT() asm volatile("cp.async.commit_group;" ::: "memory")
#define CP_WAIT0()  asm volatile("cp.async.wait_group 0;" ::: "memory")
#define CP_WAIT1()  asm volatile("cp.async.wait_group 1;" ::: "memory")

// ---------------------------------------------------------------------------
// convert: fp32 -> fp16 for inputs and weights
// ---------------------------------------------------------------------------
__global__ void __launch_bounds__(256) convert_split(const float* __restrict__ q,
                                                     const float* __restrict__ k,
                                                     const float* __restrict__ v,
                                                     const float* __restrict__ w_in,
                                                     const float* __restrict__ w_out)
{
    const size_t u = (size_t)blockIdx.x * 256 + threadIdx.x;   // float4 index
    float4 x;
    __half* dst;
    size_t e;
    if (u < 3145728) {
        const size_t z = u >> 20, off = u & 1048575;
        x = ((const float4*)((z == 0) ? q : (z == 1) ? k : v))[off];
        dst = g_inh; e = u * 4;
    } else {
        const size_t uw = u - 3145728;
        x = (uw < 786432) ? ((const float4*)w_in)[uw]
                          : ((const float4*)w_out)[uw - 786432];
        dst = g_wh; e = uw * 4;
    }
    __half h[4];
    h[0] = __float2half_rn(x.x); h[1] = __float2half_rn(x.y);
    h[2] = __float2half_rn(x.z); h[3] = __float2half_rn(x.w);
    *(uint2*)(dst + e) = *(const uint2*)h;
}

// ---------------------------------------------------------------------------
// HMMA fp16 NT GEMM 128x128 tile, K=1024, BK=32, pure fp16.
// cp.async double-buffered. smem: A 2x10240; B 2x10240 at 20480. 40960 B.
// MODE 0: QKV (z): z=0 -> q (scaled), z=1 -> k, z=2 -> v ([b][s][d] fp16).
// MODE 1: out projection -> Cout + bias (fp32).
// ---------------------------------------------------------------------------
#define HMMA_SMEM 40960

template <int MODE>
__global__ void __launch_bounds__(256, 2) hmma_gemm(const float* __restrict__ biasIn,
                                                    float* __restrict__ Cout)
{
    extern __shared__ char smem[];
    const int tid = threadIdx.x;
    const int lane = tid & 31;
    const int wid = tid >> 5;
    const int wm = wid & 3;
    const int wn = wid >> 2;
    const int bm = blockIdx.y * 128;
    const int bn = blockIdx.x * 128;
    const int z  = (MODE == 0) ? blockIdx.z : 0;

    const __half* A;
    const __half* B;
    const float* bias;
    if (MODE == 0) {
        A = g_inh + (size_t)z * 4194304;
        B = g_wh + (size_t)z * 1048576;
        bias = biasIn + z * Edim;
    } else {
        A = g_ch;
        B = g_wh + 3145728;
        bias = biasIn;
    }

    const int r0 = tid >> 2;
    const int gc = tid & 3;
    const uint32_t sb = smem_u32(smem);
    const uint32_t a_lane = (uint32_t)((wm * 32 + (lane & 15)) * 80 + (lane >> 4) * 16);
    const uint32_t b_lane = (uint32_t)((wn * 64 + (lane >> 4) * 8 + (lane & 7)) * 80
                                       + ((lane >> 3) & 1) * 16);

    float acc[2][8][4];
#pragma unroll
    for (int mt = 0; mt < 2; ++mt)
#pragma unroll
        for (int nt = 0; nt < 8; ++nt)
#pragma unroll
            for (int q = 0; q < 4; ++q) acc[mt][nt][q] = 0.f;

    auto issue = [&](int c, int buf) {
        const int k0 = c * 32;
#pragma unroll
        for (int i = 0; i < 2; ++i) {
            const int row = r0 + 64 * i;
            cpa16(sb + (uint32_t)(buf * 10240 + row * 80 + gc * 16),
                  A + (size_t)(bm + row) * Edim + k0 + gc * 8);
            cpa16(sb + (uint32_t)(20480 + buf * 10240 + row * 80 + gc * 16),
                  B + (size_t)(bn + row) * Edim + k0 + gc * 8);
        }
        CP_COMMIT();
    };

    issue(0, 0);
    issue(1, 1);

    for (int c = 0; c < 32; ++c) {
        if (c < 31) { CP_WAIT1(); } else { CP_WAIT0(); }
        __syncthreads();
        const int buf = c & 1;
        const uint32_t abase = sb + (uint32_t)buf * 10240u;
        const uint32_t bbase = sb + 20480u + (uint32_t)buf * 10240u;

#pragma unroll
        for (int k16 = 0; k16 < 2; ++k16) {
            const uint32_t koff = (uint32_t)(k16 * 32);
            uint32_t af[2][4];
#pragma unroll
            for (int mt = 0; mt < 2; ++mt)
                ldsm4(af[mt], abase + a_lane + (uint32_t)(mt * 1280) + koff);
#pragma unroll
            for (int p = 0; p < 4; ++p) {
                uint32_t bf[4];
                ldsm4(bf, bbase + b_lane + (uint32_t)(p * 1280) + koff);
#pragma unroll
                for (int mt = 0; mt < 2; ++mt) {
                    mma_f16(acc[mt][2 * p],     af[mt], bf[0], bf[1]);
                    mma_f16(acc[mt][2 * p + 1], af[mt], bf[2], bf[3]);
                }
            }
        }
        __syncthreads();
        if (c + 2 < 32) issue(c + 2, buf);
    }

    const int g  = lane >> 2;
    const int t4 = lane & 3;
#pragma unroll
    for (int mt = 0; mt < 2; ++mt) {
#pragma unroll
        for (int nt = 0; nt < 8; ++nt) {
            const int cc = bn + wn * 64 + nt * 8 + 2 * t4;
            const int rr = bm + wm * 32 + mt * 16 + g;
            const float b0 = bias[cc], b1 = bias[cc + 1];
            const float* d = acc[mt][nt];
            if (MODE == 0) {
                const int h = cc >> 6, dc = cc & 63;
                const float scale = (z == 0) ? 0.125f : 1.f;
                __half* dst = (z == 0) ? g_qh : (z == 1) ? g_kh : g_v;
#pragma unroll
                for (int rh = 0; rh < 2; ++rh) {
                    const int r = rr + 8 * rh;
                    const int l = r >> 2, n = r & 3;
                    const size_t idx = (((size_t)(n * Hh + h)) * Sdim + l) * HDim + dc;
                    *(__half2*)(dst + idx) =
                        __floats2half2_rn((d[2 * rh + 0] + b0) * scale,
                                          (d[2 * rh + 1] + b1) * scale);
                }
            } else {
#pragma unroll
                for (int rh = 0; rh < 2; ++rh) {
                    const int r = rr + 8 * rh;
                    float2 o;
                    o.x = d[2 * rh + 0] + b0;
                    o.y = d[2 * rh + 1] + b1;
                    *(float2*)(Cout + (size_t)r * Edim + cc) = o;
                }
            }
        }
    }
}

// ---------------------------------------------------------------------------
// scores_exp: one 128x128 e-tile per CTA, grid (8 sc, 8 lt, 64 b). K=64.
// Pure fp16 MMA; e staged in smem (reusing Q/K region) then stored coalesced.
// smem: Q 2kc x 10240 at 0; K same at 20480 | (after MMA) e-tile 128x272B at
// 0; zbuf at 40960. Total 41984.
// ---------------------------------------------------------------------------
#define SCORES_SMEM 41984

__global__ void __launch_bounds__(256, 2) scores_exp()
{
    extern __shared__ char smem[];
    const int tid = threadIdx.x;
    const int lane = tid & 31;
    const int wid = tid >> 5;
    const int wm = wid & 3;
    const int wn = wid >> 2;
    const int b  = blockIdx.z;
    const int bm = blockIdx.y * 128;
    const int bn = blockIdx.x * 128;
    const int sc = blockIdx.x;

    const __half* Qh = g_qh + (size_t)b * Sdim * HDim;
    const __half* Kh = g_kh + (size_t)b * Sdim * HDim;

    const int r0 = tid >> 2;
    const int gc = tid & 3;
    const uint32_t sb = smem_u32(smem);
    const uint32_t a_lane = (uint32_t)((wm * 32 + (lane & 15)) * 80 + (lane >> 4) * 16);
    const uint32_t b_lane = (uint32_t)((wn * 64 + (lane >> 4) * 8 + (lane & 7)) * 80
                                       + ((lane >> 3) & 1) * 16);
    const int g  = lane >> 2;
    const int t4 = lane & 3;

#pragma unroll
    for (int kc = 0; kc < 2; ++kc)
#pragma unroll
        for (int i = 0; i < 2; ++i) {
            const int row = r0 + 64 * i;
            cpa16(sb + (uint32_t)(kc * 10240 + row * 80 + gc * 16),
                  Qh + (size_t)(bm + row) * HDim + kc * 32 + gc * 8);
            cpa16(sb + (uint32_t)(20480 + kc * 10240 + row * 80 + gc * 16),
                  Kh + (size_t)(bn + row) * HDim + kc * 32 + gc * 8);
        }
    CP_COMMIT();
    CP_WAIT0();
    __syncthreads();

    float acc[2][8][4];
#pragma unroll
    for (int mt = 0; mt < 2; ++mt)
#pragma unroll
        for (int nt = 0; nt < 8; ++nt)
#pragma unroll
            for (int q = 0; q < 4; ++q) acc[mt][nt][q] = 0.f;

#pragma unroll
    for (int kc = 0; kc < 2; ++kc)
#pragma unroll
        for (int k16 = 0; k16 < 2; ++k16) {
            const uint32_t koff = (uint32_t)(kc * 10240 + k16 * 32);
            uint32_t af[2][4];
#pragma unroll
            for (int mt = 0; mt < 2; ++mt)
                ldsm4(af[mt], sb + koff + a_lane + (uint32_t)(mt * 1280));
#pragma unroll
            for (int p = 0; p < 4; ++p) {
                uint32_t bf[4];
                ldsm4(bf, sb + 20480u + koff + b_lane + (uint32_t)(p * 1280));
#pragma unroll
                for (int mt = 0; mt < 2; ++mt) {
                    mma_f16(acc[mt][2 * p],     af[mt], bf[0], bf[1]);
                    mma_f16(acc[mt][2 * p + 1], af[mt], bf[2], bf[3]);
                }
            }
        }

    // Q/K smem dead after this barrier; reuse it for the e-tile
    __syncthreads();

    // exp + stage e-tile [128 rows][272B stride]; accumulate partial Z
    float Zp[2][2] = {{0.f, 0.f}, {0.f, 0.f}};
#pragma unroll
    for (int mt = 0; mt < 2; ++mt)
#pragma unroll
        for (int nt = 0; nt < 8; ++nt) {
            const int cl = wn * 64 + nt * 8 + 2 * t4;
            const float* d = acc[mt][nt];
#pragma unroll
            for (int rh = 0; rh < 2; ++rh) {
                const int rl = wm * 32 + mt * 16 + g + 8 * rh;
                const float e0 = __expf(d[2 * rh + 0]);
                const float e1 = __expf(d[2 * rh + 1]);
                Zp[mt][rh] += e0 + e1;
                *(__half2*)(smem + rl * 272 + cl * 2) = __floats2half2_rn(e0, e1);
            }
        }
    __syncthreads();

    // coalesced e-tile store: 128 rows x 256B (uint4 per thread-slot)
#pragma unroll
    for (int it = 0; it < 8; ++it) {
        const int t = tid + 256 * it;
        const int row = t >> 4, seg = t & 15;
        const uint4 v = *(const uint4*)(smem + row * 272 + seg * 16);
        *(uint4*)(g_eh + ((size_t)b * Ldim + bm + row) * Sdim + bn + seg * 8) = v;
    }

    // partial Z reduction
    float* zbuf = (float*)(smem + 40960);
#pragma unroll
    for (int mt = 0; mt < 2; ++mt)
#pragma unroll
        for (int rh = 0; rh < 2; ++rh) {
            float zv = Zp[mt][rh];
            zv += __shfl_xor_sync(0xffffffffu, zv, 1);
            zv += __shfl_xor_sync(0xffffffffu, zv, 2);
            if (t4 == 0) zbuf[wn * 128 + wm * 32 + mt * 16 + rh * 8 + g] = zv;
        }
    __syncthreads();
    if (tid < 128)
        g_Zpart[(((size_t)b * Ldim) + bm + tid) * 8 + sc] = zbuf[tid] + zbuf[128 + tid];
}

// ---------------------------------------------------------------------------
// averaged attn + sigmoid outputs + invZ finalize. e in fp16.
// grid (512, 4): 2 l-rows per CTA, one uint4 e-load per head per thread.
// ---------------------------------------------------------------------------
__global__ void __launch_bounds__(256) avg_kernel(float* __restrict__ out)
{
    const int l0 = blockIdx.x * 2;
    const int n  = blockIdx.y;
    const int tid = threadIdx.x;
    const int row = tid >> 7;            // 0 or 1
    const int c8  = (tid & 127) * 8;     // 8-half segment within the row
    const int l   = l0 + row;

    __shared__ float sinv[2][16];
    if (tid < 32) {
        const int r = tid >> 4, h = tid & 15;
        const int b = n * 16 + h;
        const float* zp = g_Zpart + (((size_t)b * Ldim) + l0 + r) * 8;
        float z = 0.f;
#pragma unroll
        for (int j = 0; j < 8; ++j) z += zp[j];
        const float iz = 1.0f / z;
        sinv[r][h] = iz;
        g_invZ[(size_t)b * Ldim + l0 + r] = iz;
    }
    __syncthreads();

    float aa[8], ss[8];
#pragma unroll
    for (int j = 0; j < 8; ++j) { aa[j] = 0.f; ss[j] = 0.f; }

    for (int h = 0; h < 16; ++h) {
        const int b = n * 16 + h;
        const float invZ = sinv[row][h];
        const uint4 w = *(const uint4*)(g_eh + ((size_t)b * Ldim + l) * Sdim + c8);
        const uint32_t ws[4] = {w.x, w.y, w.z, w.w};
#pragma unroll
        for (int q = 0; q < 4; ++q) {
            const float2 e2 = __half22float2(*(const __half2*)&ws[q]);
            aa[2 * q + 0] += e2.x * invZ;
            aa[2 * q + 1] += e2.y * invZ;
            ss[2 * q + 0] += __fdividef(e2.x, e2.x + 1.f);
            ss[2 * q + 1] += __fdividef(e2.y, e2.y + 1.f);
        }
    }

    const size_t o = ((size_t)(n * Ldim) + l) * Sdim + c8;
    float4 oa0, oa1, os0, os1;
    oa0.x = aa[0] * 0.0625f; oa0.y = aa[1] * 0.0625f; oa0.z = aa[2] * 0.0625f; oa0.w = aa[3] * 0.0625f;
    oa1.x = aa[4] * 0.0625f; oa1.y = aa[5] * 0.0625f; oa1.z = aa[6] * 0.0625f; oa1.w = aa[7] * 0.0625f;
    os0.x = ss[0] * 0.0625f; os0.y = ss[1] * 0.0625f; os0.z = ss[2] * 0.0625f; os0.w = ss[3] * 0.0625f;
    os1.x = ss[4] * 0.0625f; os1.y = ss[5] * 0.0625f; os1.z = ss[6] * 0.0625f; os1.w = ss[7] * 0.0625f;
    *(float4*)&out[OUT_ATTN + o]     = oa0;
    *(float4*)&out[OUT_ATTN + o + 4] = oa1;
    *(float4*)&out[OUT_SIG  + o]     = os0;
    *(float4*)&out[OUT_SIG  + o + 4] = os1;
}

// ---------------------------------------------------------------------------
// ctx[b] = (e[b] @ v[b]) * invZ : fp16 MMA, 128x64 tile, K=1024, BK=32.
// B = v [b][s][d] consumed directly via ldmatrix.trans (no transpose pass).
// cp.async double-buffered, occ 3.
// smem: A 2x10240 at 0; B (v rows, 144B stride) 2x4608 at 20480. 29696 B.
// ---------------------------------------------------------------------------
#define CTX_SMEM 29696

__global__ void __launch_bounds__(256, 3) ctx_hmma()
{
    extern __shared__ char smem[];
    const int tid = threadIdx.x;
    const int lane = tid & 31;
    const int wid = tid >> 5;
    const int wm = wid & 3;
    const int wn = wid >> 2;
    const int b  = blockIdx.y;
    const int bm = blockIdx.x * 128;

    const __half* Ap = g_eh + (size_t)b * Ldim * Sdim;
    const __half* Vp = g_v + (size_t)b * Sdim * HDim;

    const int r0 = tid >> 2;
    const int gc = tid & 3;
    const int vr = tid >> 3;          // 0..31 v-row
    const int vg = tid & 7;           // 16B granule in 128B v-row
    const uint32_t sb = smem_u32(smem);
    const uint32_t a_lane = (uint32_t)((wm * 32 + (lane & 15)) * 80 + (lane >> 4) * 16);
    // trans-B lane addressing: rows k = (lane&15), col halves = wn*32 + (lane>>4)*8
    const uint32_t b_lane = (uint32_t)((lane & 15) * 144 + wn * 64 + (lane >> 4) * 16);

    float acc[2][4][4];
#pragma unroll
    for (int mt = 0; mt < 2; ++mt)
#pragma unroll
        for (int nt = 0; nt < 4; ++nt)
#pragma unroll
            for (int q = 0; q < 4; ++q) acc[mt][nt][q] = 0.f;

    auto issue = [&](int c, int buf) {
        const int k0 = c * 32;
#pragma unroll
        for (int i = 0; i < 2; ++i) {
            const int row = r0 + 64 * i;
            cpa16(sb + (uint32_t)(buf * 10240 + row * 80 + gc * 16),
                  Ap + (size_t)(bm + row) * Sdim + k0 + gc * 8);
        }
        // v rows: 32 rows x 128B, padded to 144B stride
        cpa16(sb + (uint32_t)(20480 + buf * 4608 + vr * 144 + vg * 16),
              Vp + (size_t)(k0 + vr) * HDim + vg * 8);
        CP_COMMIT();
    };

    issue(0, 0);
    issue(1, 1);

    for (int c = 0; c < 32; ++c) {
        if (c < 31) { CP_WAIT1(); } else { CP_WAIT0(); }
        __syncthreads();
        const int buf = c & 1;
        const uint32_t abase = sb + (uint32_t)buf * 10240u;
        const uint32_t bbase = sb + 20480u + (uint32_t)buf * 4608u;

#pragma unroll
        for (int k16 = 0; k16 < 2; ++k16) {
            uint32_t af[2][4];
#pragma unroll
            for (int mt = 0; mt < 2; ++mt)
                ldsm4(af[mt], abase + a_lane + (uint32_t)(mt * 1280) + (uint32_t)(k16 * 32));
#pragma unroll
            for (int p = 0; p < 2; ++p) {
                uint32_t bf[4];
                ldsm4t(bf, bbase + b_lane + (uint32_t)(k16 * 2304) + (uint32_t)(p * 32));
#pragma unroll
                for (int mt = 0; mt < 2; ++mt) {
                    mma_f16(acc[mt][2 * p],     af[mt], bf[0], bf[1]);
                    mma_f16(acc[mt][2 * p + 1], af[mt], bf[2], bf[3]);
                }
            }
        }
        __syncthreads();
        if (c + 2 < 32) issue(c + 2, buf);
    }

    const int n = b >> 4;
    const int h = b & 15;
    const int g  = lane >> 2;
    const int t4 = lane & 3;
    float izv[2][2];
#pragma unroll
    for (int mt = 0; mt < 2; ++mt)
#pragma unroll
        for (int rh = 0; rh < 2; ++rh)
            izv[mt][rh] = g_invZ[(size_t)b * Ldim + bm + wm * 32 + mt * 16 + g + 8 * rh];

#pragma unroll
    for (int mt = 0; mt < 2; ++mt)
#pragma unroll
        for (int nt = 0; nt < 4; ++nt) {
            const int cc = wn * 32 + nt * 8 + 2 * t4;
            const int rr = bm + wm * 32 + mt * 16 + g;
            const float* d = acc[mt][nt];
#pragma unroll
            for (int rh = 0; rh < 2; ++rh) {
                const int l = rr + 8 * rh;
                const float iz = izv[mt][rh];
                *(__half2*)(g_ch + ((size_t)(l * Nb + n)) * Edim + h * HDim + cc) =
                    __floats2half2_rn(d[2 * rh + 0] * iz, d[2 * rh + 1] * iz);
            }
        }
}

// ---------------------------------------------------------------------------
extern "C" void kernel_launch(void* const* d_in, const int* in_sizes, int n_in,
                              void* d_out, int out_size)
{
    const float* query = (const float*)d_in[0];
    const float* key   = (const float*)d_in[1];
    const float* value = (const float*)d_in[2];
    const float* w_in  = (const float*)d_in[3];
    const float* b_in  = (const float*)d_in[4];
    const float* w_out = (const float*)d_in[5];
    const float* b_out = (const float*)d_in[6];
    float* out = (float*)d_out;

    cudaFuncSetAttribute(hmma_gemm<0>, cudaFuncAttributeMaxDynamicSharedMemorySize, HMMA_SMEM);
    cudaFuncSetAttribute(hmma_gemm<1>, cudaFuncAttributeMaxDynamicSharedMemorySize, HMMA_SMEM);
    cudaFuncSetAttribute(scores_exp, cudaFuncAttributeMaxDynamicSharedMemorySize, SCORES_SMEM);
    cudaFuncSetAttribute(ctx_hmma, cudaFuncAttributeMaxDynamicSharedMemorySize, CTX_SMEM);

    const dim3 blk(256);

    convert_split<<<16384, blk>>>(query, key, value, w_in, w_out);
    hmma_gemm<0><<<dim3(8, 32, 3), blk, HMMA_SMEM>>>(b_in, nullptr);
    scores_exp<<<dim3(8, 8, Bt), blk, SCORES_SMEM>>>();
    avg_kernel<<<dim3(512, Nb), blk>>>(out);
    ctx_hmma<<<dim3(8, Bt), blk, CTX_SMEM>>>();
    hmma_gemm<1><<<dim3(8, 32), blk, HMMA_SMEM>>>(b_out, out);
}

// round 17
// speedup vs baseline: 1.1094x; 1.0805x over previous
#include <cuda_runtime.h>
#include <cuda_fp16.h>
#include <cstdint>

// Problem dims
#define Ldim 1024
#define Sdim 1024
#define Nb   4
#define Edim 1024
#define Hh   16
#define HDim 64
#define Bt   64      // Nb*Hh
#define MROWS 4096   // Ldim*Nb

// d_out layout (fp32): [0..4194304) out(L,N,E) | [..8388608) attn(N,L,S) | [..12582912) sig(N,L,S)
#define OUT_ATTN 4194304
#define OUT_SIG  8388608

// ------------------------------- scratch ----------------------------------
__device__ float g_invZ[(size_t)Bt * Ldim];
__device__ __half g_v[(size_t)Bt * Sdim * HDim];               // [b][s][d] fp16
__device__ __half g_eh[(size_t)Bt * Ldim * Sdim];              // e = exp(score) fp16
__device__ __half g_qh[(size_t)Bt * Sdim * HDim];              // q fp16 (scaled)
__device__ __half g_kh[(size_t)Bt * Sdim * HDim];              // k fp16
__device__ __half g_inh[(size_t)3 * MROWS * Edim];             // inputs fp16
__device__ __half g_wh[(size_t)4 * Edim * Edim];               // weights fp16 (w_in ++ w_out)
__device__ __half g_ch[(size_t)MROWS * Edim];                  // ctx fp16

// ------------------------------ helpers ------------------------------------
__device__ __forceinline__ uint32_t smem_u32(const void* p) {
    uint32_t a; asm("{ .reg .u64 t; cvta.to.shared.u64 t, %1; cvt.u32.u64 %0, t; }" : "=r"(a) : "l"(p));
    return a;
}
__device__ __forceinline__ void ldsm4(uint32_t* r, uint32_t addr) {
    asm volatile("ldmatrix.sync.aligned.m8n8.x4.shared.b16 {%0,%1,%2,%3}, [%4];"
                 : "=r"(r[0]), "=r"(r[1]), "=r"(r[2]), "=r"(r[3]) : "r"(addr));
}
__device__ __forceinline__ void ldsm4t(uint32_t* r, uint32_t addr) {
    asm volatile("ldmatrix.sync.aligned.m8n8.x4.trans.shared.b16 {%0,%1,%2,%3}, [%4];"
                 : "=r"(r[0]), "=r"(r[1]), "=r"(r[2]), "=r"(r[3]) : "r"(addr));
}
__device__ __forceinline__ void mma_f16(float* d, const uint32_t* a, uint32_t b0, uint32_t b1) {
    asm volatile("mma.sync.aligned.m16n8k16.row.col.f32.f16.f16.f32 "
                 "{%0,%1,%2,%3}, {%4,%5,%6,%7}, {%8,%9}, {%0,%1,%2,%3};"
                 : "+f"(d[0]), "+f"(d[1]), "+f"(d[2]), "+f"(d[3])
                 : "r"(a[0]), "r"(a[1]), "r"(a[2]), "r"(a[3]), "r"(b0), "r"(b1));
}
__device__ __forceinline__ void cpa16(uint32_t saddr, const void* g) {
    asm volatile("cp.async.cg.shared.global [%0], [%1], 16;" :: "r"(saddr), "l"(g));
}
#define CP_COMMIT() asm volatile("cp.async.commit_group;" ::: "memory")
#define CP_WAIT0()  asm volatile("cp.async.wait_group 0;" ::: "memory")
#define CP_WAIT1()  asm volatile("cp.async.wait_group 1;" ::: "memory")

__device__ __forceinline__ uint32_t packh2(float a, float bb) {
    const __half2 h = __floats2half2_rn(a, bb);
    return *(const uint32_t*)&h;
}

// ---------------------------------------------------------------------------
// convert: fp32 -> fp16 for inputs and weights
// ---------------------------------------------------------------------------
__global__ void __launch_bounds__(256) convert_split(const float* __restrict__ q,
                                                     const float* __restrict__ k,
                                                     const float* __restrict__ v,
                                                     const float* __restrict__ w_in,
                                                     const float* __restrict__ w_out)
{
    const size_t u = (size_t)blockIdx.x * 256 + threadIdx.x;   // float4 index
    float4 x;
    __half* dst;
    size_t e;
    if (u < 3145728) {
        const size_t z = u >> 20, off = u & 1048575;
        x = ((const float4*)((z == 0) ? q : (z == 1) ? k : v))[off];
        dst = g_inh; e = u * 4;
    } else {
        const size_t uw = u - 3145728;
        x = (uw < 786432) ? ((const float4*)w_in)[uw]
                          : ((const float4*)w_out)[uw - 786432];
        dst = g_wh; e = uw * 4;
    }
    __half h[4];
    h[0] = __float2half_rn(x.x); h[1] = __float2half_rn(x.y);
    h[2] = __float2half_rn(x.z); h[3] = __float2half_rn(x.w);
    *(uint2*)(dst + e) = *(const uint2*)h;
}

// ---------------------------------------------------------------------------
// HMMA fp16 NT GEMM 128x128 tile, K=1024, BK=32, pure fp16.
// cp.async double-buffered. smem: A 2x10240; B 2x10240 at 20480. 40960 B.
// MODE 0: QKV (z): z=0 -> q (scaled), z=1 -> k, z=2 -> v ([b][s][d] fp16).
// MODE 1: out projection -> Cout + bias (fp32).
// ---------------------------------------------------------------------------
#define HMMA_SMEM 40960

template <int MODE>
__global__ void __launch_bounds__(256, 2) hmma_gemm(const float* __restrict__ biasIn,
                                                    float* __restrict__ Cout)
{
    extern __shared__ char smem[];
    const int tid = threadIdx.x;
    const int lane = tid & 31;
    const int wid = tid >> 5;
    const int wm = wid & 3;
    const int wn = wid >> 2;
    const int bm = blockIdx.y * 128;
    const int bn = blockIdx.x * 128;
    const int z  = (MODE == 0) ? blockIdx.z : 0;

    const __half* A;
    const __half* B;
    const float* bias;
    if (MODE == 0) {
        A = g_inh + (size_t)z * 4194304;
        B = g_wh + (size_t)z * 1048576;
        bias = biasIn + z * Edim;
    } else {
        A = g_ch;
        B = g_wh + 3145728;
        bias = biasIn;
    }

    const int r0 = tid >> 2;
    const int gc = tid & 3;
    const uint32_t sb = smem_u32(smem);
    const uint32_t a_lane = (uint32_t)((wm * 32 + (lane & 15)) * 80 + (lane >> 4) * 16);
    const uint32_t b_lane = (uint32_t)((wn * 64 + (lane >> 4) * 8 + (lane & 7)) * 80
                                       + ((lane >> 3) & 1) * 16);

    float acc[2][8][4];
#pragma unroll
    for (int mt = 0; mt < 2; ++mt)
#pragma unroll
        for (int nt = 0; nt < 8; ++nt)
#pragma unroll
            for (int q = 0; q < 4; ++q) acc[mt][nt][q] = 0.f;

    auto issue = [&](int c, int buf) {
        const int k0 = c * 32;
#pragma unroll
        for (int i = 0; i < 2; ++i) {
            const int row = r0 + 64 * i;
            cpa16(sb + (uint32_t)(buf * 10240 + row * 80 + gc * 16),
                  A + (size_t)(bm + row) * Edim + k0 + gc * 8);
            cpa16(sb + (uint32_t)(20480 + buf * 10240 + row * 80 + gc * 16),
                  B + (size_t)(bn + row) * Edim + k0 + gc * 8);
        }
        CP_COMMIT();
    };

    issue(0, 0);
    issue(1, 1);

    for (int c = 0; c < 32; ++c) {
        if (c < 31) { CP_WAIT1(); } else { CP_WAIT0(); }
        __syncthreads();
        const int buf = c & 1;
        const uint32_t abase = sb + (uint32_t)buf * 10240u;
        const uint32_t bbase = sb + 20480u + (uint32_t)buf * 10240u;

#pragma unroll
        for (int k16 = 0; k16 < 2; ++k16) {
            const uint32_t koff = (uint32_t)(k16 * 32);
            uint32_t af[2][4];
#pragma unroll
            for (int mt = 0; mt < 2; ++mt)
                ldsm4(af[mt], abase + a_lane + (uint32_t)(mt * 1280) + koff);
#pragma unroll
            for (int p = 0; p < 4; ++p) {
                uint32_t bf[4];
                ldsm4(bf, bbase + b_lane + (uint32_t)(p * 1280) + koff);
#pragma unroll
                for (int mt = 0; mt < 2; ++mt) {
                    mma_f16(acc[mt][2 * p],     af[mt], bf[0], bf[1]);
                    mma_f16(acc[mt][2 * p + 1], af[mt], bf[2], bf[3]);
                }
            }
        }
        __syncthreads();
        if (c + 2 < 32) issue(c + 2, buf);
    }

    const int g  = lane >> 2;
    const int t4 = lane & 3;
#pragma unroll
    for (int mt = 0; mt < 2; ++mt) {
#pragma unroll
        for (int nt = 0; nt < 8; ++nt) {
            const int cc = bn + wn * 64 + nt * 8 + 2 * t4;
            const int rr = bm + wm * 32 + mt * 16 + g;
            const float b0 = bias[cc], b1 = bias[cc + 1];
            const float* d = acc[mt][nt];
            if (MODE == 0) {
                const int h = cc >> 6, dc = cc & 63;
                const float scale = (z == 0) ? 0.125f : 1.f;
                __half* dst = (z == 0) ? g_qh : (z == 1) ? g_kh : g_v;
#pragma unroll
                for (int rh = 0; rh < 2; ++rh) {
                    const int r = rr + 8 * rh;
                    const int l = r >> 2, n = r & 3;
                    const size_t idx = (((size_t)(n * Hh + h)) * Sdim + l) * HDim + dc;
                    *(__half2*)(dst + idx) =
                        __floats2half2_rn((d[2 * rh + 0] + b0) * scale,
                                          (d[2 * rh + 1] + b1) * scale);
                }
            } else {
#pragma unroll
                for (int rh = 0; rh < 2; ++rh) {
                    const int r = rr + 8 * rh;
                    float2 o;
                    o.x = d[2 * rh + 0] + b0;
                    o.y = d[2 * rh + 1] + b1;
                    *(float2*)(Cout + (size_t)r * Edim + cc) = o;
                }
            }
        }
    }
}

// ---------------------------------------------------------------------------
// Fused scores+exp+ctx: grid (8 l-tiles, 64 b). Each CTA owns 128 l-rows and
// loops over 8 s-chunks of 128. Per chunk: MMA1 e=exp(q.k) (warp = 16 l-rows
// x all 128 s), pack e-fragments in regs, MMA2 ctx += e @ V (V via
// ldmatrix.trans), stage+store e (fp16, coalesced). After all chunks the CTA
// owns full row sums: invZ computed locally, ctx scaled and stored.
// smem: Q [128][144B] at 0; K [128][144B] at 18432; V [128][144B] at 36864;
//       e-stage [128][272B] overlays K+V (18432..53248). Total 55296.
// ---------------------------------------------------------------------------
#define FUSED_SMEM 55296

__global__ void __launch_bounds__(256, 2) scores_ctx()
{
    extern __shared__ char smem[];
    const int tid  = threadIdx.x;
    const int lane = tid & 31;
    const int wm   = tid >> 5;          // 8 warps, warp owns l-rows wm*16..+15
    const int b    = blockIdx.y;
    const int bm   = blockIdx.x * 128;

    const __half* Qh = g_qh + (size_t)b * Sdim * HDim;
    const __half* Kh = g_kh + (size_t)b * Sdim * HDim;
    const __half* Vp = g_v  + (size_t)b * Sdim * HDim;

    const uint32_t sb = smem_u32(smem);
    const int g  = lane >> 2;
    const int t4 = lane & 3;

    const uint32_t a_lane  = (uint32_t)((wm * 16 + (lane & 15)) * 144 + (lane >> 4) * 16);
    const uint32_t b1_lane = (uint32_t)(((lane >> 4) * 8 + (lane & 7)) * 144 + ((lane >> 3) & 1) * 16);
    const uint32_t bt_lane = (uint32_t)((lane & 15) * 144 + (lane >> 4) * 16);

    // load Q tile once (128 rows x 128B, 144B stride)
#pragma unroll
    for (int it = 0; it < 4; ++it) {
        const int idx = tid + 256 * it;
        const int row = idx >> 3, gg = idx & 7;
        cpa16(sb + (uint32_t)(row * 144 + gg * 16),
              Qh + (size_t)(bm + row) * HDim + gg * 8);
    }

    float acc2[8][4];
#pragma unroll
    for (int nt = 0; nt < 8; ++nt)
#pragma unroll
        for (int q = 0; q < 4; ++q) acc2[nt][q] = 0.f;
    float Zp[2] = {0.f, 0.f};

    for (int sc = 0; sc < 8; ++sc) {
        const int s0 = sc * 128;
        // load K,V chunks
#pragma unroll
        for (int it = 0; it < 4; ++it) {
            const int idx = tid + 256 * it;
            const int row = idx >> 3, gg = idx & 7;
            cpa16(sb + 18432u + (uint32_t)(row * 144 + gg * 16),
                  Kh + (size_t)(s0 + row) * HDim + gg * 8);
            cpa16(sb + 36864u + (uint32_t)(row * 144 + gg * 16),
                  Vp + (size_t)(s0 + row) * HDim + gg * 8);
        }
        CP_COMMIT();
        CP_WAIT0();
        __syncthreads();

        uint32_t ea[8][4];
        // MMA1 in two s-halves of 64 (keeps acc1 at 32 regs)
#pragma unroll
        for (int hh = 0; hh < 2; ++hh) {
            float acc1[8][4];
#pragma unroll
            for (int nt = 0; nt < 8; ++nt)
#pragma unroll
                for (int q = 0; q < 4; ++q) acc1[nt][q] = 0.f;

#pragma unroll
            for (int k16 = 0; k16 < 4; ++k16) {
                uint32_t af[4];
                ldsm4(af, sb + a_lane + (uint32_t)(k16 * 32));
#pragma unroll
                for (int ns = 0; ns < 4; ++ns) {
                    uint32_t bf[4];
                    ldsm4(bf, sb + 18432u + (uint32_t)((hh * 4 + ns) * 2304)
                              + b1_lane + (uint32_t)(k16 * 32));
                    mma_f16(acc1[2 * ns],     af, bf[0], bf[1]);
                    mma_f16(acc1[2 * ns + 1], af, bf[2], bf[3]);
                }
            }
            // exp + Z + pack into A-fragments for MMA2
#pragma unroll
            for (int ns = 0; ns < 4; ++ns) {
                const int j = hh * 4 + ns;
                const float e00 = __expf(acc1[2 * ns][0]);
                const float e01 = __expf(acc1[2 * ns][1]);
                const float e02 = __expf(acc1[2 * ns][2]);
                const float e03 = __expf(acc1[2 * ns][3]);
                const float e10 = __expf(acc1[2 * ns + 1][0]);
                const float e11 = __expf(acc1[2 * ns + 1][1]);
                const float e12 = __expf(acc1[2 * ns + 1][2]);
                const float e13 = __expf(acc1[2 * ns + 1][3]);
                Zp[0] += (e00 + e01) + (e10 + e11);
                Zp[1] += (e02 + e03) + (e12 + e13);
                ea[j][0] = packh2(e00, e01);   // row g,   k lo
                ea[j][1] = packh2(e02, e03);   // row g+8, k lo
                ea[j][2] = packh2(e10, e11);   // row g,   k hi
                ea[j][3] = packh2(e12, e13);   // row g+8, k hi
            }
        }

        // MMA2: ctx += e @ V  (A from regs, B = V rows via ldmatrix.trans)
#pragma unroll
        for (int j = 0; j < 8; ++j) {
#pragma unroll
            for (int p = 0; p < 4; ++p) {
                uint32_t bf[4];
                ldsm4t(bf, sb + 36864u + (uint32_t)(j * 2304) + bt_lane + (uint32_t)(p * 32));
                mma_f16(acc2[2 * p],     ea[j], bf[0], bf[1]);
                mma_f16(acc2[2 * p + 1], ea[j], bf[2], bf[3]);
            }
        }
        __syncthreads();    // all V reads done before e-stage overwrites K+V

        // stage e from regs into [128][272B] at 18432
        {
            const int r0w = wm * 16 + g;
#pragma unroll
            for (int j = 0; j < 8; ++j) {
                const int colb = j * 16 + 2 * t4;
                *(uint32_t*)(smem + 18432 + r0w * 272 + colb * 2)       = ea[j][0];
                *(uint32_t*)(smem + 18432 + (r0w + 8) * 272 + colb * 2) = ea[j][1];
                *(uint32_t*)(smem + 18432 + r0w * 272 + (colb + 8) * 2)       = ea[j][2];
                *(uint32_t*)(smem + 18432 + (r0w + 8) * 272 + (colb + 8) * 2) = ea[j][3];
            }
        }
        __syncthreads();

        // coalesced e store: 128 rows x 256B
#pragma unroll
        for (int it = 0; it < 8; ++it) {
            const int t = tid + 256 * it;
            const int row = t >> 4, seg = t & 15;
            const uint4 v = *(const uint4*)(smem + 18432 + row * 272 + seg * 16);
            *(uint4*)(g_eh + ((size_t)b * Ldim + bm + row) * Sdim + s0 + seg * 8) = v;
        }
        __syncthreads();    // e-stage reads done before next chunk's cp.async
    }

    // Z reduce over t4 quad -> full row sums; invZ; scale+store ctx
    Zp[0] += __shfl_xor_sync(0xffffffffu, Zp[0], 1);
    Zp[0] += __shfl_xor_sync(0xffffffffu, Zp[0], 2);
    Zp[1] += __shfl_xor_sync(0xffffffffu, Zp[1], 1);
    Zp[1] += __shfl_xor_sync(0xffffffffu, Zp[1], 2);
    const float iz0 = 1.0f / Zp[0];
    const float iz1 = 1.0f / Zp[1];

    const int n = b >> 4;
    const int h = b & 15;
    const int lr0 = bm + wm * 16 + g;
    if (t4 == 0) {
        g_invZ[(size_t)b * Ldim + lr0] = iz0;
        g_invZ[(size_t)b * Ldim + lr0 + 8] = iz1;
    }

#pragma unroll
    for (int nt2 = 0; nt2 < 8; ++nt2) {
        const int col = (nt2 >> 1) * 16 + (nt2 & 1) * 8 + 2 * t4;
        const float* d = acc2[nt2];
        const __half2 o0 = __floats2half2_rn(d[0] * iz0, d[1] * iz0);
        const __half2 o1 = __floats2half2_rn(d[2] * iz1, d[3] * iz1);
        *(__half2*)(g_ch + ((size_t)(lr0 * Nb + n)) * Edim + h * 64 + col) = o0;
        *(__half2*)(g_ch + ((size_t)((lr0 + 8) * Nb + n)) * Edim + h * 64 + col) = o1;
    }
}

// ---------------------------------------------------------------------------
// averaged attn + sigmoid outputs. e in fp16; invZ precomputed by scores_ctx.
// grid (512, 4): 2 l-rows per CTA, one uint4 e-load per head per thread.
// ---------------------------------------------------------------------------
__global__ void __launch_bounds__(256) avg_kernel(float* __restrict__ out)
{
    const int l0 = blockIdx.x * 2;
    const int n  = blockIdx.y;
    const int tid = threadIdx.x;
    const int row = tid >> 7;            // 0 or 1
    const int c8  = (tid & 127) * 8;     // 8-half segment within the row
    const int l   = l0 + row;

    __shared__ float sinv[2][16];
    if (tid < 32) {
        const int r = tid >> 4, h = tid & 15;
        const int b = n * 16 + h;
        sinv[r][h] = g_invZ[(size_t)b * Ldim + l0 + r];
    }
    __syncthreads();

    float aa[8], ss[8];
#pragma unroll
    for (int j = 0; j < 8; ++j) { aa[j] = 0.f; ss[j] = 0.f; }

    for (int h = 0; h < 16; ++h) {
        const int b = n * 16 + h;
        const float invZ = sinv[row][h];
        const uint4 w = *(const uint4*)(g_eh + ((size_t)b * Ldim + l) * Sdim + c8);
        const uint32_t ws[4] = {w.x, w.y, w.z, w.w};
#pragma unroll
        for (int q = 0; q < 4; ++q) {
            const float2 e2 = __half22float2(*(const __half2*)&ws[q]);
            aa[2 * q + 0] += e2.x * invZ;
            aa[2 * q + 1] += e2.y * invZ;
            ss[2 * q + 0] += __fdividef(e2.x, e2.x + 1.f);
            ss[2 * q + 1] += __fdividef(e2.y, e2.y + 1.f);
        }
    }

    const size_t o = ((size_t)(n * Ldim) + l) * Sdim + c8;
    float4 oa0, oa1, os0, os1;
    oa0.x = aa[0] * 0.0625f; oa0.y = aa[1] * 0.0625f; oa0.z = aa[2] * 0.0625f; oa0.w = aa[3] * 0.0625f;
    oa1.x = aa[4] * 0.0625f; oa1.y = aa[5] * 0.0625f; oa1.z = aa[6] * 0.0625f; oa1.w = aa[7] * 0.0625f;
    os0.x = ss[0] * 0.0625f; os0.y = ss[1] * 0.0625f; os0.z = ss[2] * 0.0625f; os0.w = ss[3] * 0.0625f;
    os1.x = ss[4] * 0.0625f; os1.y = ss[5] * 0.0625f; os1.z = ss[6] * 0.0625f; os1.w = ss[7] * 0.0625f;
    *(float4*)&out[OUT_ATTN + o]     = oa0;
    *(float4*)&out[OUT_ATTN + o + 4] = oa1;
    *(float4*)&out[OUT_SIG  + o]     = os0;
    *(float4*)&out[OUT_SIG  + o + 4] = os1;
}

// ---------------------------------------------------------------------------
extern "C" void kernel_launch(void* const* d_in, const int* in_sizes, int n_in,
                              void* d_out, int out_size)
{
    const float* query = (const float*)d_in[0];
    const float* key   = (const float*)d_in[1];
    const float* value = (const float*)d_in[2];
    const float* w_in  = (const float*)d_in[3];
    const float* b_in  = (const float*)d_in[4];
    const float* w_out = (const float*)d_in[5];
    const float* b_out = (const float*)d_in[6];
    float* out = (float*)d_out;

    cudaFuncSetAttribute(hmma_gemm<0>, cudaFuncAttributeMaxDynamicSharedMemorySize, HMMA_SMEM);
    cudaFuncSetAttribute(hmma_gemm<1>, cudaFuncAttributeMaxDynamicSharedMemorySize, HMMA_SMEM);
    cudaFuncSetAttribute(scores_ctx, cudaFuncAttributeMaxDynamicSharedMemorySize, FUSED_SMEM);

    const dim3 blk(256);

    convert_split<<<16384, blk>>>(query, key, value, w_in, w_out);
    hmma_gemm<0><<<dim3(8, 32, 3), blk, HMMA_SMEM>>>(b_in, nullptr);
    scores_ctx<<<dim3(8, Bt), blk, FUSED_SMEM>>>();
    avg_kernel<<<dim3(512, Nb), blk>>>(out);
    hmma_gemm<1><<<dim3(8, 32), blk, HMMA_SMEM>>>(b_out, out);
}